// round 2
// baseline (speedup 1.0000x reference)
#include <cuda_runtime.h>
#include <math.h>

#define NROWS 32768   // B*N
#define CCH   256

// ---------------- scratch (device globals; no allocation allowed) ----------
__device__ float g_qsum[NROWS * CCH];
__device__ float g_gate[NROWS * CCH];
__device__ float g_ksum[NROWS * CCH];
__device__ float g_v   [NROWS * CCH];
__device__ float g_vloc[NROWS * CCH];
__device__ float g_t   [NROWS * CCH];
__device__ float g_Sp  [8 * 64 * 1024];   // split-K partials of S
__device__ float g_S   [64 * 1024];       // S[b*8+h][d*32+e]

// ---------------- helpers ---------------------------------------------------
__device__ __forceinline__ float spow(float a, float p) {
    float aa = fabsf(a);
    if (aa == 0.0f) return 0.0f;
    if (p == 3.0f) return aa * aa * aa;   // fast path (power_p == 0 case)
    return powf(aa, p);
}

// ---------------- 128x64 fp32 GEMM core (K=256, BK=32) ----------------------
__device__ __forceinline__ void gemm_core(const float* __restrict__ A,
                                          const float* __restrict__ Bp,
                                          int ldb, float acc[8][4])
{
    __shared__ float As[32 * 132];   // transposed: As[k][m], padded row 132
    __shared__ float Bs[32 * 64];    // Bs[k][n]

    const int tid = threadIdx.x;
    const int m0 = (tid >> 4) * 8;
    const int n0 = (tid & 15) * 4;
    const int rowBase = blockIdx.x * 128;

#pragma unroll
    for (int i = 0; i < 8; i++)
#pragma unroll
        for (int j = 0; j < 4; j++) acc[i][j] = 0.0f;

    for (int kt = 0; kt < 256; kt += 32) {
#pragma unroll
        for (int p = 0; p < 4; p++) {
            int idx = tid + p * 256;
            int m   = idx >> 3;
            int c4  = (idx & 7) * 4;
            float4 a = *(const float4*)(A + (size_t)(rowBase + m) * 256 + kt + c4);
            As[(c4 + 0) * 132 + m] = a.x;
            As[(c4 + 1) * 132 + m] = a.y;
            As[(c4 + 2) * 132 + m] = a.z;
            As[(c4 + 3) * 132 + m] = a.w;
        }
#pragma unroll
        for (int p = 0; p < 2; p++) {
            int idx = tid + p * 256;
            int k   = idx >> 4;
            int nn4 = (idx & 15) * 4;
            float4 bv = *(const float4*)(Bp + (size_t)(kt + k) * ldb + nn4);
            *(float4*)(Bs + k * 64 + nn4) = bv;
        }
        __syncthreads();

#pragma unroll
        for (int k = 0; k < 32; k++) {
            float4 b4  = *(const float4*)(Bs + k * 64 + n0);
            float4 alo = *(const float4*)(As + k * 132 + m0);
            float4 ahi = *(const float4*)(As + k * 132 + m0 + 4);
            float av[8] = {alo.x, alo.y, alo.z, alo.w, ahi.x, ahi.y, ahi.z, ahi.w};
#pragma unroll
            for (int i = 0; i < 8; i++) {
                acc[i][0] += av[i] * b4.x;
                acc[i][1] += av[i] * b4.y;
                acc[i][2] += av[i] * b4.z;
                acc[i][3] += av[i] * b4.w;
            }
        }
        __syncthreads();
    }
}

// ---------------- kernel 1: x @ [Wqg | Wkv] with pow/gate epilogue ----------
__global__ void __launch_bounds__(256)
k_gemm_qgkv(const float* __restrict__ x, const float* __restrict__ Wqg,
            const float* __restrict__ Wkv, const float* __restrict__ power_p)
{
    const int j0 = blockIdx.y * 64;                 // global col in [0,1024)
    const float* Bp = (j0 < 512) ? (Wqg + j0) : (Wkv + (j0 - 512));

    float acc[8][4];
    gemm_core(x, Bp, 512, acc);

    const int tid = threadIdx.x;
    const int m0 = (tid >> 4) * 8;
    const int n0 = (tid & 15) * 4;
    const int rowBase = blockIdx.x * 128;
    const int seg   = j0 >> 8;                      // 0:q 1:gate 2:k 3:v
    const int cbase = (j0 & 255) + n0;              // channel base

    float pw[4];
    if (seg == 0 || seg == 2) {
#pragma unroll
        for (int j = 0; j < 4; j++) {
            float pp = power_p[cbase + j];
            pw[j] = 1.0f + 4.0f / (1.0f + expf(-pp));
        }
    }
    float* dst = (seg == 0) ? g_qsum : (seg == 1) ? g_gate
               : (seg == 2) ? g_ksum : g_v;

#pragma unroll
    for (int i = 0; i < 8; i++) {
        int r = rowBase + m0 + i;
        float4 o;
        if (seg == 0 || seg == 2) {
            o.x = spow(acc[i][0], pw[0]);
            o.y = spow(acc[i][1], pw[1]);
            o.z = spow(acc[i][2], pw[2]);
            o.w = spow(acc[i][3], pw[3]);
        } else {
            o.x = acc[i][0]; o.y = acc[i][1]; o.z = acc[i][2]; o.w = acc[i][3];
        }
        *(float4*)(dst + (size_t)r * 256 + cbase) = o;
    }
}

// ---------------- kernel 2: S partials = k_sum^T v per (b,h), split-K -------
__global__ void __launch_bounds__(256) k_kv_outer()
{
    __shared__ float Ks[64 * 32];
    __shared__ float Vs[64 * 32];

    const int bh = blockIdx.x;       // 0..63
    const int s  = blockIdx.y;       // 0..7 split over N
    const int b = bh >> 3, h = bh & 7;
    const int tid = threadIdx.x;
    const int e  = tid & 31;
    const int dq = (tid >> 5) * 4;

    float a0 = 0.f, a1 = 0.f, a2 = 0.f, a3 = 0.f;
    const size_t base = ((size_t)(b * 4096 + s * 512)) * 256 + h * 32;

    for (int ch = 0; ch < 8; ch++) {
        int n0 = ch * 64;
#pragma unroll
        for (int p = 0; p < 8; p++) {
            int idx = tid + p * 256;
            int nl = idx >> 5, c = idx & 31;
            size_t g = base + (size_t)(n0 + nl) * 256 + c;
            Ks[idx] = g_ksum[g];
            Vs[idx] = g_v[g];
        }
        __syncthreads();
#pragma unroll
        for (int nl = 0; nl < 64; nl++) {
            float4 kq = *(const float4*)(Ks + nl * 32 + dq);
            float  ve = Vs[nl * 32 + e];
            a0 += kq.x * ve; a1 += kq.y * ve; a2 += kq.z * ve; a3 += kq.w * ve;
        }
        __syncthreads();
    }
    float* dst = g_Sp + ((size_t)s * 64 + bh) * 1024;
    dst[(dq + 0) * 32 + e] = a0;
    dst[(dq + 1) * 32 + e] = a1;
    dst[(dq + 2) * 32 + e] = a2;
    dst[(dq + 3) * 32 + e] = a3;
}

__global__ void k_reduceS()
{
    int i = blockIdx.x * 1024 + threadIdx.x;   // grid 64 x 1024 threads
    float s = 0.f;
#pragma unroll
    for (int p = 0; p < 8; p++) s += g_Sp[(size_t)p * 65536 + i];
    g_S[i] = s;
}

// ---------------- kernel 3: depthwise 5x5 conv (reference's exact permuted
// image space).  Image (i, ch): i = b*8 + (n>>9), ch = (n>>4)&31,
// pixel (r, c): r = (n&15)*4 + (u>>6), c = u&63, where u = h*32+hd.
// For fixed r, row pixels c=0..63 are CONTIGUOUS in g_v:
//   X[r][c] = g_v[(b*4096 + n(r))*256 + (r&3)*64 + c],  n(r) = base_n | (r>>2)
// Output pixel (r,c) lands at final channel cc = ch*8 + h2, n_out = r*64+c.
__global__ void __launch_bounds__(256)
k_conv(const float* __restrict__ dwc_w, const float* __restrict__ dwc_b)
{
    __shared__ float Sin[68 * 68];

    const int blk = blockIdx.x;          // 0..2047
    const int ch = blk & 31, i = blk >> 5;
    const int b = i >> 3, h2 = i & 7;
    const int base_n = (h2 << 9) | (ch << 4);
    const int tid = threadIdx.x;

    for (int idx = tid; idx < 68 * 68; idx += 256) {
        int row = idx / 68;
        int col = idx - row * 68;
        int gr = row - 2, gc = col - 2;
        float v = 0.0f;
        if (gr >= 0 && gr < 64 && gc >= 0 && gc < 64) {
            int n = base_n | (gr >> 2);
            v = g_v[((size_t)(b * 4096 + n)) * 256 + (gr & 3) * 64 + gc];
        }
        Sin[idx] = v;
    }
    float w[25];
#pragma unroll
    for (int t = 0; t < 25; t++) w[t] = dwc_w[ch * 25 + t];
    float bias = dwc_b[ch];
    __syncthreads();

    const int c  = tid & 63;
    const int r0 = tid >> 6;             // 0..3
#pragma unroll
    for (int j = 0; j < 16; j++) {
        int r = r0 * 16 + j;
        float sum = bias;
#pragma unroll
        for (int kr = 0; kr < 5; kr++)
#pragma unroll
            for (int kc = 0; kc < 5; kc++)
                sum += w[kr * 5 + kc] * Sin[(r + kr) * 68 + (c + kc)];
        int n_out = r * 64 + c;
        g_vloc[((size_t)(b * 4096 + n_out)) * 256 + ch * 8 + h2] = sum;
    }
}

// ---------------- kernel 4: t = (q_sum @ S + v_loc) * gate -------------------
__global__ void __launch_bounds__(256) k_combine()
{
    __shared__ float Ss[8192];          // S for this batch (8 heads x 1024)
    __shared__ float qs[256], vl[256], gg[256];

    const int tid = threadIdx.x;
    const int r0 = blockIdx.x * 16;
    const int b  = r0 >> 12;

#pragma unroll
    for (int p = 0; p < 32; p++)
        Ss[tid + p * 256] = g_S[(size_t)b * 8192 + tid + p * 256];
    __syncthreads();

    const int h = tid >> 5, e = tid & 31;
    float Sc[32];
#pragma unroll
    for (int d = 0; d < 32; d++) Sc[d] = Ss[h * 1024 + d * 32 + e];

    const int c = tid;

    for (int ri = 0; ri < 16; ri++) {
        int r = r0 + ri;
        qs[tid] = g_qsum[(size_t)r * 256 + tid];
        vl[tid] = g_vloc[(size_t)r * 256 + tid];
        gg[tid] = g_gate[(size_t)r * 256 + tid];
        __syncthreads();
        float acc = 0.f;
#pragma unroll
        for (int d = 0; d < 32; d++) acc += qs[h * 32 + d] * Sc[d];
        g_t[(size_t)r * 256 + c] = (acc + vl[c]) * gg[c];
        __syncthreads();
    }
}

// ---------------- kernel 5: out = t @ Wproj + b ------------------------------
__global__ void __launch_bounds__(256)
k_gemm_proj(const float* __restrict__ Wproj, const float* __restrict__ bproj,
            float* __restrict__ out)
{
    const int j0 = blockIdx.y * 64;
    float acc[8][4];
    gemm_core(g_t, Wproj + j0, 256, acc);

    const int tid = threadIdx.x;
    const int m0 = (tid >> 4) * 8;
    const int n0 = (tid & 15) * 4;
    const int rowBase = blockIdx.x * 128;
    const int jb = j0 + n0;

    float4 bb = *(const float4*)(bproj + jb);
#pragma unroll
    for (int i = 0; i < 8; i++) {
        int r = rowBase + m0 + i;
        float4 o;
        o.x = acc[i][0] + bb.x;
        o.y = acc[i][1] + bb.y;
        o.z = acc[i][2] + bb.z;
        o.w = acc[i][3] + bb.w;
        *(float4*)(out + (size_t)r * 256 + jb) = o;
    }
}

// ---------------- launch -----------------------------------------------------
extern "C" void kernel_launch(void* const* d_in, const int* in_sizes, int n_in,
                              void* d_out, int out_size)
{
    const float* x     = (const float*)d_in[0];
    const float* Wqg   = (const float*)d_in[1];
    const float* Wkv   = (const float*)d_in[2];
    const float* Wproj = (const float*)d_in[3];
    const float* bproj = (const float*)d_in[4];
    const float* dwcw  = (const float*)d_in[5];
    const float* dwcb  = (const float*)d_in[6];
    const float* pp    = (const float*)d_in[7];
    float* out = (float*)d_out;

    k_gemm_qgkv<<<dim3(256, 16), 256>>>(x, Wqg, Wkv, pp);
    k_kv_outer <<<dim3(64, 8),  256>>>();
    k_conv     <<<2048, 256>>>(dwcw, dwcb);
    k_reduceS  <<<64, 1024>>>();
    k_combine  <<<2048, 256>>>();
    k_gemm_proj<<<dim3(256, 4), 256>>>(Wproj, bproj, out);
}

// round 5
// speedup vs baseline: 1.6691x; 1.6691x over previous
#include <cuda_runtime.h>
#include <cuda_bf16.h>
#include <math.h>
#include <stdint.h>

#define NROWS 32768   // B*N
#define CCH   256

// ---------------- scratch (device globals; no allocation allowed) ----------
__device__ float g_qsum[NROWS * CCH];
__device__ float g_gate[NROWS * CCH];
__device__ float g_ksum[NROWS * CCH];
__device__ float g_v   [NROWS * CCH];
__device__ float g_vloc[NROWS * CCH];
__device__ float g_t   [NROWS * CCH];
__device__ float g_Sp  [8 * 64 * 1024];
__device__ float g_S   [64 * 1024];

// ---------------- helpers ----------------------------------------------------
__device__ __forceinline__ float spow(float a, float p) {
    float aa = fabsf(a);
    if (aa == 0.0f) return 0.0f;
    if (p == 3.0f) return aa * aa * aa;
    return powf(aa, p);
}

__device__ __forceinline__ uint32_t smem_u32(const void* p) {
    uint32_t a;
    asm("{ .reg .u64 t; cvta.to.shared.u64 t, %1; cvt.u32.u64 %0, t; }" : "=r"(a) : "l"(p));
    return a;
}

__device__ __forceinline__ void ldsm_x4(uint32_t* r, uint32_t addr) {
    asm volatile("ldmatrix.sync.aligned.m8n8.x4.shared.b16 {%0,%1,%2,%3}, [%4];"
        : "=r"(r[0]), "=r"(r[1]), "=r"(r[2]), "=r"(r[3]) : "r"(addr));
}
__device__ __forceinline__ void ldsm_x4_t(uint32_t* r, uint32_t addr) {
    asm volatile("ldmatrix.sync.aligned.m8n8.x4.trans.shared.b16 {%0,%1,%2,%3}, [%4];"
        : "=r"(r[0]), "=r"(r[1]), "=r"(r[2]), "=r"(r[3]) : "r"(addr));
}
__device__ __forceinline__ void mma_bf16(float* c, const uint32_t* a,
                                         uint32_t b0, uint32_t b1) {
    asm volatile("mma.sync.aligned.m16n8k16.row.col.f32.bf16.bf16.f32 "
        "{%0,%1,%2,%3}, {%4,%5,%6,%7}, {%8,%9}, {%0,%1,%2,%3};"
        : "+f"(c[0]), "+f"(c[1]), "+f"(c[2]), "+f"(c[3])
        : "r"(a[0]), "r"(a[1]), "r"(a[2]), "r"(a[3]), "r"(b0), "r"(b1));
}

__device__ __forceinline__ void split2(float x, uint16_t& h, uint16_t& l) {
    __nv_bfloat16 hb = __float2bfloat16_rn(x);
    float hf = __bfloat162float(hb);
    __nv_bfloat16 lb = __float2bfloat16_rn(x - hf);
    h = __bfloat16_as_ushort(hb);
    l = __bfloat16_as_ushort(lb);
}

#define A_STRIDE 40   // halves per A smem row (80 bytes: 16B-aligned for ldmatrix)
#define B_STRIDE 136  // halves per B smem row (272 bytes: 16B-aligned)

// ---------------- split-bf16 mma.sync GEMM -----------------------------------
// mode 0: A=x [32768,256], B=[Wqg|Wkv] ldb=512, N=1024; epilogue pow/gate.
// mode 1: A=g_t, B=Wproj ldb=256, N=256; epilogue +bias -> out.
// CTA tile 128x128, 8 warps (64m x 32n each), K-block 32.
// 3 passes: hi*hi, hi*lo, lo*hi (bf16 split of fp32, error ~2^-17/term).
__global__ void __launch_bounds__(256)
k_gemm_mma(const float* __restrict__ Ain, const float* __restrict__ B1,
           const float* __restrict__ B2, const float* __restrict__ power_p,
           const float* __restrict__ bias, float* __restrict__ out, int mode)
{
    __shared__ __align__(16) uint16_t sAh[128 * A_STRIDE];
    __shared__ __align__(16) uint16_t sAl[128 * A_STRIDE];
    __shared__ __align__(16) uint16_t sBh[32 * B_STRIDE];
    __shared__ __align__(16) uint16_t sBl[32 * B_STRIDE];
    __shared__ float pwsh[128];

    const int tid = threadIdx.x, wid = tid >> 5, lane = tid & 31;
    const int rowBase = blockIdx.x * 128;
    const int j0 = blockIdx.y * 128;

    const float* A = (mode == 0) ? Ain : g_t;
    const float* Bp;
    int ldb;
    if (mode == 0) { Bp = (j0 < 512) ? (B1 + j0) : (B2 + (j0 - 512)); ldb = 512; }
    else           { Bp = B1 + j0; ldb = 256; }

    const int seg = (mode == 0) ? (j0 >> 8) : -1;
    const bool dopow = (seg == 0 || seg == 2);
    if (dopow && tid < 128) {
        float pp = power_p[(j0 & 255) + tid];
        pwsh[tid] = 1.0f + 4.0f / (1.0f + expf(-pp));
    }

    float acc[4][4][4];
#pragma unroll
    for (int mt = 0; mt < 4; mt++)
#pragma unroll
        for (int nt = 0; nt < 4; nt++)
#pragma unroll
            for (int q = 0; q < 4; q++) acc[mt][nt][q] = 0.0f;

    const int wm = (wid >> 2) * 64;
    const int wn = (wid & 3) * 32;

    const uint32_t aAh = smem_u32(sAh), aAl = smem_u32(sAl);
    const uint32_t aBh = smem_u32(sBh), aBl = smem_u32(sBl);
    // ldmatrix per-lane bases (bytes)
    const uint32_t aoff = (uint32_t)((wm + (lane & 15)) * (A_STRIDE * 2) + (lane >> 4) * 16);
    const uint32_t boff = (uint32_t)(((lane & 7) + 8 * ((lane >> 3) & 1)) * (B_STRIDE * 2)
                                     + (lane >> 4) * 16 + wn * 2);

    for (int kt = 0; kt < 256; kt += 32) {
        // ---- load + split A tile: 128 rows x 32 k ----
#pragma unroll
        for (int p = 0; p < 4; p++) {
            int idx = p * 256 + tid;
            int row = idx >> 3, c4 = (idx & 7) * 4;
            float4 a = *(const float4*)(A + (size_t)(rowBase + row) * 256 + kt + c4);
            uint16_t h0, h1, h2, h3, l0, l1, l2, l3;
            split2(a.x, h0, l0); split2(a.y, h1, l1);
            split2(a.z, h2, l2); split2(a.w, h3, l3);
            int s = row * A_STRIDE + c4;
            *(uint32_t*)&sAh[s]     = (uint32_t)h0 | ((uint32_t)h1 << 16);
            *(uint32_t*)&sAh[s + 2] = (uint32_t)h2 | ((uint32_t)h3 << 16);
            *(uint32_t*)&sAl[s]     = (uint32_t)l0 | ((uint32_t)l1 << 16);
            *(uint32_t*)&sAl[s + 2] = (uint32_t)l2 | ((uint32_t)l3 << 16);
        }
        // ---- load + split B tile: 32 k x 128 n (k-major) ----
#pragma unroll
        for (int p = 0; p < 4; p++) {
            int idx = p * 256 + tid;
            int k = idx >> 5, n4 = (idx & 31) * 4;
            float4 b = *(const float4*)(Bp + (size_t)(kt + k) * ldb + n4);
            uint16_t h0, h1, h2, h3, l0, l1, l2, l3;
            split2(b.x, h0, l0); split2(b.y, h1, l1);
            split2(b.z, h2, l2); split2(b.w, h3, l3);
            int s = k * B_STRIDE + n4;
            *(uint32_t*)&sBh[s]     = (uint32_t)h0 | ((uint32_t)h1 << 16);
            *(uint32_t*)&sBh[s + 2] = (uint32_t)h2 | ((uint32_t)h3 << 16);
            *(uint32_t*)&sBl[s]     = (uint32_t)l0 | ((uint32_t)l1 << 16);
            *(uint32_t*)&sBl[s + 2] = (uint32_t)l2 | ((uint32_t)l3 << 16);
        }
        __syncthreads();

#pragma unroll
        for (int ks = 0; ks < 2; ks++) {
#pragma unroll
            for (int pass = 0; pass < 3; pass++) {
                uint32_t ab = ((pass == 2) ? aAl : aAh) + aoff + ks * 32;
                uint32_t bb = ((pass == 1) ? aBl : aBh) + boff + ks * 16 * (B_STRIDE * 2);
                uint32_t af[4][4];
#pragma unroll
                for (int mt = 0; mt < 4; mt++) ldsm_x4(af[mt], ab + mt * 16 * (A_STRIDE * 2));
                uint32_t bf[2][4];
#pragma unroll
                for (int np = 0; np < 2; np++) ldsm_x4_t(bf[np], bb + np * 32);
#pragma unroll
                for (int mt = 0; mt < 4; mt++)
#pragma unroll
                    for (int nt = 0; nt < 4; nt++)
                        mma_bf16(acc[mt][nt], af[mt],
                                 bf[nt >> 1][(nt & 1) * 2], bf[nt >> 1][(nt & 1) * 2 + 1]);
            }
        }
        __syncthreads();
    }

    // ---- epilogue ----
    const int g = lane >> 2, tg = lane & 3;
    float* dst = nullptr;
    if (mode == 0)
        dst = (seg == 0) ? g_qsum : (seg == 1) ? g_gate : (seg == 2) ? g_ksum : g_v;

#pragma unroll
    for (int mt = 0; mt < 4; mt++) {
#pragma unroll
        for (int nt = 0; nt < 4; nt++) {
            int lc = wn + nt * 8 + 2 * tg;          // local col 0..127
            int row0 = rowBase + wm + mt * 16 + g;
            float v0 = acc[mt][nt][0], v1 = acc[mt][nt][1];
            float v2 = acc[mt][nt][2], v3 = acc[mt][nt][3];
            if (mode == 0) {
                int chan = (j0 & 255) + lc;
                if (dopow) {
                    float p0 = pwsh[lc], p1 = pwsh[lc + 1];
                    v0 = spow(v0, p0); v1 = spow(v1, p1);
                    v2 = spow(v2, p0); v3 = spow(v3, p1);
                }
                *(float2*)(dst + (size_t)row0 * 256 + chan)       = make_float2(v0, v1);
                *(float2*)(dst + (size_t)(row0 + 8) * 256 + chan) = make_float2(v2, v3);
            } else {
                int gcol = j0 + lc;
                float b0 = bias[gcol], b1 = bias[gcol + 1];
                *(float2*)(out + (size_t)row0 * 256 + gcol)       = make_float2(v0 + b0, v1 + b1);
                *(float2*)(out + (size_t)(row0 + 8) * 256 + gcol) = make_float2(v2 + b0, v3 + b1);
            }
        }
    }
}

// ---------------- kernel 2: S partials = k_sum^T v per (b,h), split-K -------
__global__ void __launch_bounds__(256) k_kv_outer()
{
    __shared__ float Ks[64 * 32];
    __shared__ float Vs[64 * 32];

    const int bh = blockIdx.x;
    const int s  = blockIdx.y;
    const int b = bh >> 3, h = bh & 7;
    const int tid = threadIdx.x;
    const int e  = tid & 31;
    const int dq = (tid >> 5) * 4;

    float a0 = 0.f, a1 = 0.f, a2 = 0.f, a3 = 0.f;
    const size_t base = ((size_t)(b * 4096 + s * 512)) * 256 + h * 32;

    for (int ch = 0; ch < 8; ch++) {
        int n0 = ch * 64;
#pragma unroll
        for (int p = 0; p < 8; p++) {
            int idx = tid + p * 256;
            int nl = idx >> 5, c = idx & 31;
            size_t gg = base + (size_t)(n0 + nl) * 256 + c;
            Ks[idx] = g_ksum[gg];
            Vs[idx] = g_v[gg];
        }
        __syncthreads();
#pragma unroll
        for (int nl = 0; nl < 64; nl++) {
            float4 kq = *(const float4*)(Ks + nl * 32 + dq);
            float  ve = Vs[nl * 32 + e];
            a0 += kq.x * ve; a1 += kq.y * ve; a2 += kq.z * ve; a3 += kq.w * ve;
        }
        __syncthreads();
    }
    float* dstp = g_Sp + ((size_t)s * 64 + bh) * 1024;
    dstp[(dq + 0) * 32 + e] = a0;
    dstp[(dq + 1) * 32 + e] = a1;
    dstp[(dq + 2) * 32 + e] = a2;
    dstp[(dq + 3) * 32 + e] = a3;
}

__global__ void k_reduceS()
{
    int i = blockIdx.x * 1024 + threadIdx.x;
    float s = 0.f;
#pragma unroll
    for (int p = 0; p < 8; p++) s += g_Sp[(size_t)p * 65536 + i];
    g_S[i] = s;
}

// ---------------- kernel 3: depthwise 5x5 conv (permuted image space) -------
__global__ void __launch_bounds__(256)
k_conv(const float* __restrict__ dwc_w, const float* __restrict__ dwc_b)
{
    __shared__ float Sin[68 * 68];

    const int blk = blockIdx.x;
    const int ch = blk & 31, i = blk >> 5;
    const int b = i >> 3, h2 = i & 7;
    const int base_n = (h2 << 9) | (ch << 4);
    const int tid = threadIdx.x;

    for (int idx = tid; idx < 68 * 68; idx += 256) {
        int row = idx / 68;
        int col = idx - row * 68;
        int gr = row - 2, gc = col - 2;
        float v = 0.0f;
        if (gr >= 0 && gr < 64 && gc >= 0 && gc < 64) {
            int n = base_n | (gr >> 2);
            v = g_v[((size_t)(b * 4096 + n)) * 256 + (gr & 3) * 64 + gc];
        }
        Sin[idx] = v;
    }
    float w[25];
#pragma unroll
    for (int t = 0; t < 25; t++) w[t] = dwc_w[ch * 25 + t];
    float bias = dwc_b[ch];
    __syncthreads();

    const int c  = tid & 63;
    const int r0 = tid >> 6;
#pragma unroll
    for (int j = 0; j < 16; j++) {
        int r = r0 * 16 + j;
        float sum = bias;
#pragma unroll
        for (int kr = 0; kr < 5; kr++)
#pragma unroll
            for (int kc = 0; kc < 5; kc++)
                sum += w[kr * 5 + kc] * Sin[(r + kr) * 68 + (c + kc)];
        int n_out = r * 64 + c;
        g_vloc[((size_t)(b * 4096 + n_out)) * 256 + ch * 8 + h2] = sum;
    }
}

// ---------------- kernel 4: t = (q_sum @ S + v_loc) * gate -------------------
__global__ void __launch_bounds__(256) k_combine()
{
    __shared__ float Ss[8192];
    __shared__ float qs[256], vl[256], gg[256];

    const int tid = threadIdx.x;
    const int r0 = blockIdx.x * 16;
    const int b  = r0 >> 12;

#pragma unroll
    for (int p = 0; p < 32; p++)
        Ss[tid + p * 256] = g_S[(size_t)b * 8192 + tid + p * 256];
    __syncthreads();

    const int h = tid >> 5, e = tid & 31;
    float Sc[32];
#pragma unroll
    for (int d = 0; d < 32; d++) Sc[d] = Ss[h * 1024 + d * 32 + e];

    const int c = tid;

    for (int ri = 0; ri < 16; ri++) {
        int r = r0 + ri;
        qs[tid] = g_qsum[(size_t)r * 256 + tid];
        vl[tid] = g_vloc[(size_t)r * 256 + tid];
        gg[tid] = g_gate[(size_t)r * 256 + tid];
        __syncthreads();
        float acc = 0.f;
#pragma unroll
        for (int d = 0; d < 32; d++) acc += qs[h * 32 + d] * Sc[d];
        g_t[(size_t)r * 256 + c] = (acc + vl[c]) * gg[c];
        __syncthreads();
    }
}

// ---------------- launch -----------------------------------------------------
extern "C" void kernel_launch(void* const* d_in, const int* in_sizes, int n_in,
                              void* d_out, int out_size)
{
    const float* x     = (const float*)d_in[0];
    const float* Wqg   = (const float*)d_in[1];
    const float* Wkv   = (const float*)d_in[2];
    const float* Wproj = (const float*)d_in[3];
    const float* bproj = (const float*)d_in[4];
    const float* dwcw  = (const float*)d_in[5];
    const float* dwcb  = (const float*)d_in[6];
    const float* pp    = (const float*)d_in[7];
    float* out = (float*)d_out;

    // mode 0: qg/kv GEMM + pow epilogue
    k_gemm_mma<<<dim3(256, 8), 256>>>(x, Wqg, Wkv, pp, nullptr, nullptr, 0);
    k_kv_outer <<<dim3(64, 8),  256>>>();
    k_conv     <<<2048, 256>>>(dwcw, dwcb);
    k_reduceS  <<<64, 1024>>>();
    k_combine  <<<2048, 256>>>();
    // mode 1: proj GEMM (A = g_t selected in-kernel via mode)
    k_gemm_mma<<<dim3(256, 2), 256>>>(nullptr, Wproj, nullptr, nullptr, bproj, out, 1);
}